// round 2
// baseline (speedup 1.0000x reference)
#include <cuda_runtime.h>
#include <cuda_bf16.h>

// Problem constants
#define N_   100000
#define E_   1600000
#define IN_  64
#define H_   128
#define O_   64

// ---------------- scratch (device globals; no allocation allowed) -------------
__device__ float g_degp[N_];
__device__ float g_degn[N_];
__device__ float g_dinvp[N_];
__device__ float g_dinvn[N_];
__device__ float g_hps[N_ * H_];   // hp * dinvp  (layer-1 pos, pre-scaled)
__device__ float g_hns[N_ * H_];   // hn * dinvn
__device__ float g_h  [N_ * H_];   // layer-1 accumulator, then relu'd hidden
__device__ float g_gps[N_ * O_];   // gp * dinvp  (layer-2)
__device__ float g_gns[N_ * O_];

// ---------------- helpers ------------------------------------------------------
__device__ __forceinline__ void red_add_v4(float* p, float a, float b, float c, float d) {
    asm volatile("red.global.add.v4.f32 [%0], {%1,%2,%3,%4};"
                 :: "l"(p), "f"(a), "f"(b), "f"(c), "f"(d) : "memory");
}

__device__ __forceinline__ void fma2(unsigned long long& acc,
                                     unsigned long long w,
                                     unsigned long long xx) {
    asm("fma.rn.f32x2 %0, %1, %2, %0;" : "+l"(acc) : "l"(w), "l"(xx));
}

__device__ __forceinline__ unsigned long long pack2(float x) {
    unsigned long long r;
    asm("mov.b64 %0, {%1, %1};" : "=l"(r) : "f"(x));
    return r;
}

__device__ __forceinline__ void unpack2(unsigned long long v, float& lo, float& hi) {
    asm("mov.b64 {%0, %1}, %2;" : "=f"(lo), "=f"(hi) : "l"(v));
}

// ---------------- degree / dinv -----------------------------------------------
__global__ void k_zero_deg(int n) {
    int i = blockIdx.x * blockDim.x + threadIdx.x;
    if (i < n) { g_degp[i] = 0.f; g_degn[i] = 0.f; }
}

__global__ void k_deg(const int* __restrict__ ei, const float* __restrict__ w, int E) {
    int e = blockIdx.x * blockDim.x + threadIdx.x;
    if (e >= E) return;
    float we = w[e];
    int t = ei[E + e];
    if (we > 0.f)      atomicAdd(&g_degp[t], we);
    else if (we < 0.f) atomicAdd(&g_degn[t], -we);
}

__global__ void k_dinv(int n) {
    int i = blockIdx.x * blockDim.x + threadIdx.x;
    if (i < n) {
        g_dinvp[i] = rsqrtf(g_degp[i] + 1.0f);
        g_dinvn[i] = rsqrtf(g_degn[i] + 1.0f);
    }
}

// ---------------- GEMM layer 1: x[N,64] -> (hp,hn)[N,128] ----------------------
// packed f32x2: lane t holds (W1p[t,:], W1n[t,:]) column; 64 rows per block, R=8.
#define SMEM1 (2 * IN_ * H_ * 4 + 64 * IN_ * 4)   // 64KB weights + 16KB x = 80KB
__global__ __launch_bounds__(128) void k_gemm1(
    const float* __restrict__ x,
    const float* __restrict__ W1p, const float* __restrict__ b1p,
    const float* __restrict__ W1n, const float* __restrict__ b1n, int n)
{
    extern __shared__ float sm[];
    unsigned long long* ws = (unsigned long long*)sm;  // [IN_][H_] packed (p,n)
    float* xs = sm + 2 * IN_ * H_;                     // [64][IN_]
    const int tid = threadIdx.x;

    for (int i = tid; i < IN_ * H_; i += 128) {
        int t = i & (H_ - 1);
        int k = i >> 7;
        union { float2 f; unsigned long long u; } cv;
        cv.f = make_float2(W1p[t * IN_ + k], W1n[t * IN_ + k]);
        ws[k * H_ + t] = cv.u;
    }
    const int base = blockIdx.x * 64;
    float4* xs4 = (float4*)xs;
    for (int i = tid; i < 64 * (IN_ / 4); i += 128) {   // 1024 float4
        int r = i >> 4;
        int row = base + r;
        float4 v = make_float4(0.f, 0.f, 0.f, 0.f);
        if (row < n) v = ((const float4*)x)[row * (IN_ / 4) + (i & 15)];
        xs4[i] = v;
    }
    __syncthreads();

    const float bp = b1p[tid], bn = b1n[tid];

    for (int r0 = 0; r0 < 64; r0 += 8) {
        unsigned long long acc[8];
        #pragma unroll
        for (int j = 0; j < 8; j++) acc[j] = 0ull;

        #pragma unroll 4
        for (int k4 = 0; k4 < IN_ / 4; k4++) {
            float4 xv[8];
            #pragma unroll
            for (int j = 0; j < 8; j++)
                xv[j] = *(const float4*)&xs[(r0 + j) * IN_ + 4 * k4];
            #pragma unroll
            for (int kk = 0; kk < 4; kk++) {
                unsigned long long wv = ws[(4 * k4 + kk) * H_ + tid];
                #pragma unroll
                for (int j = 0; j < 8; j++) {
                    float xe = (kk == 0) ? xv[j].x : (kk == 1) ? xv[j].y
                             : (kk == 2) ? xv[j].z : xv[j].w;
                    fma2(acc[j], wv, pack2(xe));
                }
            }
        }

        #pragma unroll
        for (int j = 0; j < 8; j++) {
            int row = base + r0 + j;
            if (row < n) {
                float ap, an;
                unpack2(acc[j], ap, an);
                float dp = g_dinvp[row], dn = g_dinvn[row];
                int idx = row * H_ + tid;
                g_hps[idx] = ap * dp;
                g_hns[idx] = an * dn;
                // init accumulator with self-loop + bias terms
                g_h[idx] = ap * dp * dp + bp - an * dn * dn - bn;
            }
        }
    }
}

// ---------------- edge aggregation layer 1 (warp per edge, F=128) --------------
__global__ __launch_bounds__(256) void k_edge1(const int* __restrict__ ei,
                                               const float* __restrict__ w, int E)
{
    int wid = (blockIdx.x * blockDim.x + threadIdx.x) >> 5;
    if (wid >= E) return;
    int lane = threadIdx.x & 31;
    int s = __ldg(ei + wid);
    int t = __ldg(ei + E + wid);
    float we = __ldg(w + wid);
    const float* src;
    float scale;
    if (we >= 0.f) { src = g_hps; scale = we * g_dinvp[t]; }
    else           { src = g_hns; scale = we * g_dinvn[t]; }   // we<0 supplies the minus sign
    float4 v = __ldg((const float4*)(src + s * H_) + lane);
    red_add_v4(g_h + t * H_ + lane * 4,
               v.x * scale, v.y * scale, v.z * scale, v.w * scale);
}

__global__ void k_relu_h(int n4) {
    int i = blockIdx.x * blockDim.x + threadIdx.x;
    if (i >= n4) return;
    float4 v = ((float4*)g_h)[i];
    v.x = fmaxf(v.x, 0.f); v.y = fmaxf(v.y, 0.f);
    v.z = fmaxf(v.z, 0.f); v.w = fmaxf(v.w, 0.f);
    ((float4*)g_h)[i] = v;
}

// ---------------- GEMM layer 2: h[N,128] -> (gp,gn)[N,64] ----------------------
#define SMEM2 (2 * H_ * O_ * 4 + 64 * H_ * 4)   // 64KB weights + 32KB x = 96KB
__global__ __launch_bounds__(128) void k_gemm2(
    const float* __restrict__ W2p, const float* __restrict__ b2p,
    const float* __restrict__ W2n, const float* __restrict__ b2n,
    float* __restrict__ out, int n)
{
    extern __shared__ float sm[];
    unsigned long long* ws = (unsigned long long*)sm;  // [H_][O_] packed (p,n)
    float* xs = sm + 2 * H_ * O_;                      // [64][H_]
    const int tid = threadIdx.x;
    const int o = tid & 63;
    const int half = tid >> 6;

    for (int i = tid; i < H_ * O_; i += 128) {
        int oo = i & 63;
        int k = i >> 6;
        union { float2 f; unsigned long long u; } cv;
        cv.f = make_float2(W2p[oo * H_ + k], W2n[oo * H_ + k]);
        ws[k * O_ + oo] = cv.u;
    }
    const int base = blockIdx.x * 64;
    float4* xs4 = (float4*)xs;
    for (int i = tid; i < 64 * (H_ / 4); i += 128) {   // 2048 float4
        int r = i >> 5;
        int row = base + r;
        float4 v = make_float4(0.f, 0.f, 0.f, 0.f);
        if (row < n) v = ((const float4*)g_h)[row * (H_ / 4) + (i & 31)];
        xs4[i] = v;
    }
    __syncthreads();

    const float bp = b2p[o], bn = b2n[o];

    for (int r0 = half * 32; r0 < half * 32 + 32; r0 += 8) {
        unsigned long long acc[8];
        #pragma unroll
        for (int j = 0; j < 8; j++) acc[j] = 0ull;

        #pragma unroll 4
        for (int k4 = 0; k4 < H_ / 4; k4++) {
            float4 xv[8];
            #pragma unroll
            for (int j = 0; j < 8; j++)
                xv[j] = *(const float4*)&xs[(r0 + j) * H_ + 4 * k4];
            #pragma unroll
            for (int kk = 0; kk < 4; kk++) {
                unsigned long long wv = ws[(4 * k4 + kk) * O_ + o];
                #pragma unroll
                for (int j = 0; j < 8; j++) {
                    float xe = (kk == 0) ? xv[j].x : (kk == 1) ? xv[j].y
                             : (kk == 2) ? xv[j].z : xv[j].w;
                    fma2(acc[j], wv, pack2(xe));
                }
            }
        }

        #pragma unroll
        for (int j = 0; j < 8; j++) {
            int row = base + r0 + j;
            if (row < n) {
                float ap, an;
                unpack2(acc[j], ap, an);
                float dp = g_dinvp[row], dn = g_dinvn[row];
                int idx = row * O_ + o;
                g_gps[idx] = ap * dp;
                g_gns[idx] = an * dn;
                out[idx] = ap * dp * dp + bp - an * dn * dn - bn;  // acc2 init
            }
        }
    }
}

// ---------------- edge aggregation layer 2 (16 lanes per edge, F=64) -----------
__global__ __launch_bounds__(256) void k_edge2(const int* __restrict__ ei,
                                               const float* __restrict__ w,
                                               float* __restrict__ out, int E)
{
    int gid = blockIdx.x * blockDim.x + threadIdx.x;
    int e = gid >> 4;
    if (e >= E) return;
    int sub = gid & 15;
    int s = __ldg(ei + e);
    int t = __ldg(ei + E + e);
    float we = __ldg(w + e);
    const float* src;
    float scale;
    if (we >= 0.f) { src = g_gps; scale = we * g_dinvp[t]; }
    else           { src = g_gns; scale = we * g_dinvn[t]; }
    float4 v = __ldg((const float4*)(src + s * O_) + sub);
    red_add_v4(out + t * O_ + sub * 4,
               v.x * scale, v.y * scale, v.z * scale, v.w * scale);
}

__global__ void k_relu_out(float* __restrict__ out, int n4) {
    int i = blockIdx.x * blockDim.x + threadIdx.x;
    if (i >= n4) return;
    float4 v = ((float4*)out)[i];
    v.x = fmaxf(v.x, 0.f); v.y = fmaxf(v.y, 0.f);
    v.z = fmaxf(v.z, 0.f); v.w = fmaxf(v.w, 0.f);
    ((float4*)out)[i] = v;
}

// ---------------- launch --------------------------------------------------------
extern "C" void kernel_launch(void* const* d_in, const int* in_sizes, int n_in,
                              void* d_out, int out_size)
{
    const float* x   = (const float*)d_in[0];
    const int*   ei  = (const int*)  d_in[1];
    const float* w   = (const float*)d_in[2];
    const float* W1p = (const float*)d_in[3];
    const float* b1p = (const float*)d_in[4];
    const float* W1n = (const float*)d_in[5];
    const float* b1n = (const float*)d_in[6];
    const float* W2p = (const float*)d_in[7];
    const float* b2p = (const float*)d_in[8];
    const float* W2n = (const float*)d_in[9];
    const float* b2n = (const float*)d_in[10];
    float* out = (float*)d_out;

    const int n = in_sizes[0] / IN_;
    const int E = in_sizes[2];

    cudaFuncSetAttribute(k_gemm1, cudaFuncAttributeMaxDynamicSharedMemorySize, SMEM1);
    cudaFuncSetAttribute(k_gemm2, cudaFuncAttributeMaxDynamicSharedMemorySize, SMEM2);

    k_zero_deg<<<(n + 255) / 256, 256>>>(n);
    k_deg<<<(E + 255) / 256, 256>>>(ei, w, E);
    k_dinv<<<(n + 255) / 256, 256>>>(n);

    k_gemm1<<<(n + 63) / 64, 128, SMEM1>>>(x, W1p, b1p, W1n, b1n, n);
    k_edge1<<<(E + 7) / 8, 256>>>(ei, w, E);
    k_relu_h<<<(n * H_ / 4 + 255) / 256, 256>>>(n * H_ / 4);

    k_gemm2<<<(n + 63) / 64, 128, SMEM2>>>(W2p, b2p, W2n, b2n, out, n);
    k_edge2<<<(E * 16 + 255) / 256, 256>>>(ei, w, out, E);
    k_relu_out<<<(n * O_ / 4 + 255) / 256, 256>>>(out, n * O_ / 4);
}